// round 15
// baseline (speedup 1.0000x reference)
#include <cuda_runtime.h>

// RoI max pooling, modular binning (math identical to R11-R14, all rel_err == 0):
//   y1 = rint(rois[1]/16); x1 = rint(rois[2]/16)
//   y2 = min(rint(rois[3]/16), 49); x2 = min(rint(rois[4]/16), 49)
//   bin(i,j) = max over {y = y1+i+7k <= y2, x = x1+j+7m <= x2}
//   pad bins (i >= ft_h%7 !=0 or j >= ft_w%7 !=0): max(val, 0); empty bins -> 0 via pad.
//
// R14 analysis: NCHW gather => ~10 L1 wavefronts per warp-LDG; LSU/wavefront
// throughput bound at ~50% of everything. R15: transpose to NHWC once (L2-resident),
// then every tap LDG is 32 consecutive channels = 1 aligned 128B line = 1 wavefront.

#define H_OUT 7
#define W_OUT 7
#define C_DIM 512
#define H_IN  50
#define W_IN  50
#define P_IN  (H_IN * W_IN)       // 2500
#define N_BATCH 2
#define CGRP  32                  // channels per block (lane dim)

// 10.24 MB NHWC scratch: xt[b][p][c]
__device__ float g_xt[N_BATCH * P_IN * C_DIM];

// ---------------- Pass 1: NCHW -> NHWC transpose (tiled) ----------------
__global__ __launch_bounds__(256)
void transpose_nchw_nhwc(const float* __restrict__ in) {
    __shared__ float t[32][33];
    const int b  = blockIdx.z;
    const int p0 = blockIdx.x * 32;
    const int c0 = blockIdx.y * 32;
    const int tx = threadIdx.x, ty = threadIdx.y;   // block (32, 8)

    const float* src = in   + b * (C_DIM * P_IN);
    float*       dst = g_xt + b * (P_IN * C_DIM);

    #pragma unroll
    for (int k = 0; k < 4; k++) {
        int c = c0 + ty + 8 * k;
        int p = p0 + tx;
        if (p < P_IN) t[ty + 8 * k][tx] = src[c * P_IN + p];
    }
    __syncthreads();
    #pragma unroll
    for (int k = 0; k < 4; k++) {
        int p = p0 + ty + 8 * k;
        int c = c0 + tx;
        if (p < P_IN) dst[p * C_DIM + c] = t[tx][ty + 8 * k];
    }
}

// ---------------- Pass 2: RoI pool from NHWC ----------------
// block (32, 7): lane = channel-in-group, ty = bin row i. Thread computes all 7 j bins.
__global__ __launch_bounds__(CGRP * H_OUT)
void roi_pool_nhwc(const float* __restrict__ rois, float* __restrict__ out) {
    const int lane = threadIdx.x;           // 0..31 -> channel
    const int i    = threadIdx.y;           // 0..6  (warp-uniform: warp == one i)
    const int c0   = blockIdx.x * CGRP;
    const int r    = blockIdx.y;

    __shared__ int s_b, s_y1, s_x1, s_dy, s_dx;
    __shared__ float s_out[CGRP * H_OUT * W_OUT];   // [lane][bin], stride 49 (odd) => conflict-free

    if (threadIdx.x == 0 && threadIdx.y == 0) {
        const float* rp = rois + r * 5;
        int b  = (int)rp[0];
        int y1 = (int)rintf(rp[1] * 0.0625f);   // rintf = round half-even (jnp.round)
        int x1 = (int)rintf(rp[2] * 0.0625f);
        int y2 = min((int)rintf(rp[3] * 0.0625f), H_IN - 1);
        int x2 = min((int)rintf(rp[4] * 0.0625f), W_IN - 1);
        s_b = b; s_y1 = y1; s_x1 = x1; s_dy = y2 - y1; s_dx = x2 - x1;
    }
    __syncthreads();

    const int dy = s_dy, dx = s_dx;

    // tap counts: rows fired for this i, taps per j (one div each)
    const int qh = dy / 7, rh = dy - qh * 7;
    const int ny = qh + ((i <= rh) ? 1 : 0);            // 0..4, warp-uniform
    const int qw = dx / 7, rw = dx - qw * 7;

    // base: xt[b][ (y1+i)*50 + x1 ][ c0+lane ]
    const float* base = g_xt + ((s_b * H_IN + s_y1 + i) * W_IN + s_x1) * C_DIM + c0 + lane;
    const int KY_STRIDE = 7 * W_IN * C_DIM;             // 7 image rows
    const int KX_STRIDE = 7 * C_DIM;                    // 7 pixels

    const float NEG_INF = __int_as_float(0xff800000);
    const int ft_h = dy + 1, ft_w = dx + 1;
    const int rem_h = ft_h % 7, rem_w = ft_w % 7;
    const bool padi = (rem_h != 0) && (i >= rem_h);

    #pragma unroll
    for (int j = 0; j < 7; j++) {
        const int nx = qw + ((j <= rw) ? 1 : 0);        // taps in x for bin j
        float mj = NEG_INF;
        const float* pj = base + j * C_DIM;
        for (int ky = 0; ky < ny; ky++) {               // uniform runtime trip
            const float* rp2 = pj + ky * KY_STRIDE;
            #pragma unroll
            for (int kx = 0; kx < 4; kx++) {            // predicated, all 1-wavefront LDGs
                if (kx < nx) mj = fmaxf(mj, __ldg(rp2 + kx * KX_STRIDE));
            }
        }
        const bool pad = padi || ((rem_w != 0) && (j >= rem_w));
        if (pad) mj = fmaxf(mj, 0.0f);                  // also turns empty(-inf) bins into 0
        s_out[lane * (H_OUT * W_OUT) + i * W_OUT + j] = mj;
    }
    __syncthreads();

    // coalesced linear store of the 32x49 block region
    float* o = out + (r * C_DIM + c0) * (H_OUT * W_OUT);
    const int tid = threadIdx.y * CGRP + threadIdx.x;   // 0..223
    #pragma unroll
    for (int idx = tid; idx < CGRP * H_OUT * W_OUT; idx += CGRP * H_OUT)
        o[idx] = s_out[idx];
}

extern "C" void kernel_launch(void* const* d_in, const int* in_sizes, int n_in,
                              void* d_out, int out_size) {
    const float* x    = (const float*)d_in[0];   // (2, 512, 50, 50) f32
    const float* rois = (const float*)d_in[1];   // (R, 5) f32
    float* out        = (float*)d_out;           // (R, 512, 7, 7) f32

    int R = in_sizes[1] / 5;                     // 128

    dim3 tb(32, 8);
    dim3 tg((P_IN + 31) / 32, C_DIM / 32, N_BATCH);   // 79 x 16 x 2
    transpose_nchw_nhwc<<<tg, tb>>>(x);

    dim3 block(CGRP, H_OUT);                     // 32 x 7 = 224 threads
    dim3 grid(C_DIM / CGRP, R);                  // 16 x 128 = 2048 blocks
    roi_pool_nhwc<<<grid, block>>>(rois, out);
}

// round 16
// speedup vs baseline: 1.0137x; 1.0137x over previous
#include <cuda_runtime.h>

// RoI max pooling, modular binning (math identical to R11-R14, all rel_err == 0):
//   y1 = rint(rois[1]/16); x1 = rint(rois[2]/16)
//   y2 = min(rint(rois[3]/16), 49); x2 = min(rint(rois[4]/16), 49)
//   bin(i,j) = max over {y = y1+i+7k <= y2, x = x1+j+7m <= x2}
//   pad bins (i >= ft_h%7 !=0 or j >= ft_w%7 !=0): max(val, 0); empty bins -> 0 via pad.
//
// R14 analysis: NCHW gather => ~10 L1 wavefronts per warp-LDG; LSU/wavefront
// throughput bound at ~50% of everything. R15: transpose to NHWC once (L2-resident),
// then every tap LDG is 32 consecutive channels = 1 aligned 128B line = 1 wavefront.

#define H_OUT 7
#define W_OUT 7
#define C_DIM 512
#define H_IN  50
#define W_IN  50
#define P_IN  (H_IN * W_IN)       // 2500
#define N_BATCH 2
#define CGRP  32                  // channels per block (lane dim)

// 10.24 MB NHWC scratch: xt[b][p][c]
__device__ float g_xt[N_BATCH * P_IN * C_DIM];

// ---------------- Pass 1: NCHW -> NHWC transpose (tiled) ----------------
__global__ __launch_bounds__(256)
void transpose_nchw_nhwc(const float* __restrict__ in) {
    __shared__ float t[32][33];
    const int b  = blockIdx.z;
    const int p0 = blockIdx.x * 32;
    const int c0 = blockIdx.y * 32;
    const int tx = threadIdx.x, ty = threadIdx.y;   // block (32, 8)

    const float* src = in   + b * (C_DIM * P_IN);
    float*       dst = g_xt + b * (P_IN * C_DIM);

    #pragma unroll
    for (int k = 0; k < 4; k++) {
        int c = c0 + ty + 8 * k;
        int p = p0 + tx;
        if (p < P_IN) t[ty + 8 * k][tx] = src[c * P_IN + p];
    }
    __syncthreads();
    #pragma unroll
    for (int k = 0; k < 4; k++) {
        int p = p0 + ty + 8 * k;
        int c = c0 + tx;
        if (p < P_IN) dst[p * C_DIM + c] = t[tx][ty + 8 * k];
    }
}

// ---------------- Pass 2: RoI pool from NHWC ----------------
// block (32, 7): lane = channel-in-group, ty = bin row i. Thread computes all 7 j bins.
__global__ __launch_bounds__(CGRP * H_OUT)
void roi_pool_nhwc(const float* __restrict__ rois, float* __restrict__ out) {
    const int lane = threadIdx.x;           // 0..31 -> channel
    const int i    = threadIdx.y;           // 0..6  (warp-uniform: warp == one i)
    const int c0   = blockIdx.x * CGRP;
    const int r    = blockIdx.y;

    __shared__ int s_b, s_y1, s_x1, s_dy, s_dx;
    __shared__ float s_out[CGRP * H_OUT * W_OUT];   // [lane][bin], stride 49 (odd) => conflict-free

    if (threadIdx.x == 0 && threadIdx.y == 0) {
        const float* rp = rois + r * 5;
        int b  = (int)rp[0];
        int y1 = (int)rintf(rp[1] * 0.0625f);   // rintf = round half-even (jnp.round)
        int x1 = (int)rintf(rp[2] * 0.0625f);
        int y2 = min((int)rintf(rp[3] * 0.0625f), H_IN - 1);
        int x2 = min((int)rintf(rp[4] * 0.0625f), W_IN - 1);
        s_b = b; s_y1 = y1; s_x1 = x1; s_dy = y2 - y1; s_dx = x2 - x1;
    }
    __syncthreads();

    const int dy = s_dy, dx = s_dx;

    // tap counts: rows fired for this i, taps per j (one div each)
    const int qh = dy / 7, rh = dy - qh * 7;
    const int ny = qh + ((i <= rh) ? 1 : 0);            // 0..4, warp-uniform
    const int qw = dx / 7, rw = dx - qw * 7;

    // base: xt[b][ (y1+i)*50 + x1 ][ c0+lane ]
    const float* base = g_xt + ((s_b * H_IN + s_y1 + i) * W_IN + s_x1) * C_DIM + c0 + lane;
    const int KY_STRIDE = 7 * W_IN * C_DIM;             // 7 image rows
    const int KX_STRIDE = 7 * C_DIM;                    // 7 pixels

    const float NEG_INF = __int_as_float(0xff800000);
    const int ft_h = dy + 1, ft_w = dx + 1;
    const int rem_h = ft_h % 7, rem_w = ft_w % 7;
    const bool padi = (rem_h != 0) && (i >= rem_h);

    #pragma unroll
    for (int j = 0; j < 7; j++) {
        const int nx = qw + ((j <= rw) ? 1 : 0);        // taps in x for bin j
        float mj = NEG_INF;
        const float* pj = base + j * C_DIM;
        for (int ky = 0; ky < ny; ky++) {               // uniform runtime trip
            const float* rp2 = pj + ky * KY_STRIDE;
            #pragma unroll
            for (int kx = 0; kx < 4; kx++) {            // predicated, all 1-wavefront LDGs
                if (kx < nx) mj = fmaxf(mj, __ldg(rp2 + kx * KX_STRIDE));
            }
        }
        const bool pad = padi || ((rem_w != 0) && (j >= rem_w));
        if (pad) mj = fmaxf(mj, 0.0f);                  // also turns empty(-inf) bins into 0
        s_out[lane * (H_OUT * W_OUT) + i * W_OUT + j] = mj;
    }
    __syncthreads();

    // coalesced linear store of the 32x49 block region
    float* o = out + (r * C_DIM + c0) * (H_OUT * W_OUT);
    const int tid = threadIdx.y * CGRP + threadIdx.x;   // 0..223
    #pragma unroll
    for (int idx = tid; idx < CGRP * H_OUT * W_OUT; idx += CGRP * H_OUT)
        o[idx] = s_out[idx];
}

extern "C" void kernel_launch(void* const* d_in, const int* in_sizes, int n_in,
                              void* d_out, int out_size) {
    const float* x    = (const float*)d_in[0];   // (2, 512, 50, 50) f32
    const float* rois = (const float*)d_in[1];   // (R, 5) f32
    float* out        = (float*)d_out;           // (R, 512, 7, 7) f32

    int R = in_sizes[1] / 5;                     // 128

    dim3 tb(32, 8);
    dim3 tg((P_IN + 31) / 32, C_DIM / 32, N_BATCH);   // 79 x 16 x 2
    transpose_nchw_nhwc<<<tg, tb>>>(x);

    dim3 block(CGRP, H_OUT);                     // 32 x 7 = 224 threads
    dim3 grid(C_DIM / CGRP, R);                  // 16 x 128 = 2048 blocks
    roi_pool_nhwc<<<grid, block>>>(rois, out);
}

// round 17
// speedup vs baseline: 1.0327x; 1.0187x over previous
#include <cuda_runtime.h>

// RoI max pooling, modular binning (math identical to R11-R14, all rel_err == 0):
//   y1 = rint(rois[1]/16); x1 = rint(rois[2]/16)
//   y2 = min(rint(rois[3]/16), 49); x2 = min(rint(rois[4]/16), 49)
//   bin(i,j) = max over {y = y1+i+7k <= y2, x = x1+j+7m <= x2}
//   pad bins (i >= ft_h%7 !=0 or j >= ft_w%7 !=0): max(val, 0); empty bins -> 0 via pad.
//
// R14 analysis: NCHW gather => ~10 L1 wavefronts per warp-LDG; LSU/wavefront
// throughput bound at ~50% of everything. R15: transpose to NHWC once (L2-resident),
// then every tap LDG is 32 consecutive channels = 1 aligned 128B line = 1 wavefront.

#define H_OUT 7
#define W_OUT 7
#define C_DIM 512
#define H_IN  50
#define W_IN  50
#define P_IN  (H_IN * W_IN)       // 2500
#define N_BATCH 2
#define CGRP  32                  // channels per block (lane dim)

// 10.24 MB NHWC scratch: xt[b][p][c]
__device__ float g_xt[N_BATCH * P_IN * C_DIM];

// ---------------- Pass 1: NCHW -> NHWC transpose (tiled) ----------------
__global__ __launch_bounds__(256)
void transpose_nchw_nhwc(const float* __restrict__ in) {
    __shared__ float t[32][33];
    const int b  = blockIdx.z;
    const int p0 = blockIdx.x * 32;
    const int c0 = blockIdx.y * 32;
    const int tx = threadIdx.x, ty = threadIdx.y;   // block (32, 8)

    const float* src = in   + b * (C_DIM * P_IN);
    float*       dst = g_xt + b * (P_IN * C_DIM);

    #pragma unroll
    for (int k = 0; k < 4; k++) {
        int c = c0 + ty + 8 * k;
        int p = p0 + tx;
        if (p < P_IN) t[ty + 8 * k][tx] = src[c * P_IN + p];
    }
    __syncthreads();
    #pragma unroll
    for (int k = 0; k < 4; k++) {
        int p = p0 + ty + 8 * k;
        int c = c0 + tx;
        if (p < P_IN) dst[p * C_DIM + c] = t[tx][ty + 8 * k];
    }
}

// ---------------- Pass 2: RoI pool from NHWC ----------------
// block (32, 7): lane = channel-in-group, ty = bin row i. Thread computes all 7 j bins.
__global__ __launch_bounds__(CGRP * H_OUT)
void roi_pool_nhwc(const float* __restrict__ rois, float* __restrict__ out) {
    const int lane = threadIdx.x;           // 0..31 -> channel
    const int i    = threadIdx.y;           // 0..6  (warp-uniform: warp == one i)
    const int c0   = blockIdx.x * CGRP;
    const int r    = blockIdx.y;

    __shared__ int s_b, s_y1, s_x1, s_dy, s_dx;
    __shared__ float s_out[CGRP * H_OUT * W_OUT];   // [lane][bin], stride 49 (odd) => conflict-free

    if (threadIdx.x == 0 && threadIdx.y == 0) {
        const float* rp = rois + r * 5;
        int b  = (int)rp[0];
        int y1 = (int)rintf(rp[1] * 0.0625f);   // rintf = round half-even (jnp.round)
        int x1 = (int)rintf(rp[2] * 0.0625f);
        int y2 = min((int)rintf(rp[3] * 0.0625f), H_IN - 1);
        int x2 = min((int)rintf(rp[4] * 0.0625f), W_IN - 1);
        s_b = b; s_y1 = y1; s_x1 = x1; s_dy = y2 - y1; s_dx = x2 - x1;
    }
    __syncthreads();

    const int dy = s_dy, dx = s_dx;

    // tap counts: rows fired for this i, taps per j (one div each)
    const int qh = dy / 7, rh = dy - qh * 7;
    const int ny = qh + ((i <= rh) ? 1 : 0);            // 0..4, warp-uniform
    const int qw = dx / 7, rw = dx - qw * 7;

    // base: xt[b][ (y1+i)*50 + x1 ][ c0+lane ]
    const float* base = g_xt + ((s_b * H_IN + s_y1 + i) * W_IN + s_x1) * C_DIM + c0 + lane;
    const int KY_STRIDE = 7 * W_IN * C_DIM;             // 7 image rows
    const int KX_STRIDE = 7 * C_DIM;                    // 7 pixels

    const float NEG_INF = __int_as_float(0xff800000);
    const int ft_h = dy + 1, ft_w = dx + 1;
    const int rem_h = ft_h % 7, rem_w = ft_w % 7;
    const bool padi = (rem_h != 0) && (i >= rem_h);

    #pragma unroll
    for (int j = 0; j < 7; j++) {
        const int nx = qw + ((j <= rw) ? 1 : 0);        // taps in x for bin j
        float mj = NEG_INF;
        const float* pj = base + j * C_DIM;
        for (int ky = 0; ky < ny; ky++) {               // uniform runtime trip
            const float* rp2 = pj + ky * KY_STRIDE;
            #pragma unroll
            for (int kx = 0; kx < 4; kx++) {            // predicated, all 1-wavefront LDGs
                if (kx < nx) mj = fmaxf(mj, __ldg(rp2 + kx * KX_STRIDE));
            }
        }
        const bool pad = padi || ((rem_w != 0) && (j >= rem_w));
        if (pad) mj = fmaxf(mj, 0.0f);                  // also turns empty(-inf) bins into 0
        s_out[lane * (H_OUT * W_OUT) + i * W_OUT + j] = mj;
    }
    __syncthreads();

    // coalesced linear store of the 32x49 block region
    float* o = out + (r * C_DIM + c0) * (H_OUT * W_OUT);
    const int tid = threadIdx.y * CGRP + threadIdx.x;   // 0..223
    #pragma unroll
    for (int idx = tid; idx < CGRP * H_OUT * W_OUT; idx += CGRP * H_OUT)
        o[idx] = s_out[idx];
}

extern "C" void kernel_launch(void* const* d_in, const int* in_sizes, int n_in,
                              void* d_out, int out_size) {
    const float* x    = (const float*)d_in[0];   // (2, 512, 50, 50) f32
    const float* rois = (const float*)d_in[1];   // (R, 5) f32
    float* out        = (float*)d_out;           // (R, 512, 7, 7) f32

    int R = in_sizes[1] / 5;                     // 128

    dim3 tb(32, 8);
    dim3 tg((P_IN + 31) / 32, C_DIM / 32, N_BATCH);   // 79 x 16 x 2
    transpose_nchw_nhwc<<<tg, tb>>>(x);

    dim3 block(CGRP, H_OUT);                     // 32 x 7 = 224 threads
    dim3 grid(C_DIM / CGRP, R);                  // 16 x 128 = 2048 blocks
    roi_pool_nhwc<<<grid, block>>>(rois, out);
}